// round 15
// baseline (speedup 1.0000x reference)
#include <cuda_runtime.h>
#include <cuda_bf16.h>
#include <cstdint>

#define NB 64
#define NT 512
#define NI 128
#define NH 256
#define NR 20
#define NDA 50
#define NC 10
#define G4 1024

// ----------------------------- device scratch ------------------------------
__device__ float g_S   [NB * NR * NT];              // [b][r][t]
__device__ float g_E   [NB * NT * NR];              // [b][t][r]
__device__ float g_Dinv[NB * NT * NR];              // [b][t][r]
__device__ float g_MT  [(size_t)NT * NI * NB];      // [t][i][b]
__device__ float g_hT  [NH * 64];                   // final h [hd][b]
__device__ unsigned g_flags[128];                   // per-CTA step flags
// gate-partial inboxes: [consumer 128][phase 2][src 8][kseg 2][b 4][128 cols]
__device__ float g_inbox[(size_t)128 * 2 * 8 * 2 * 4 * 128];

__device__ __forceinline__ void ffma2(unsigned long long& acc,
                                      unsigned long long a,
                                      unsigned long long b) {
    asm("fma.rn.f32x2 %0, %1, %2, %0;" : "+l"(acc) : "l"(a), "l"(b));
}
__device__ __forceinline__ float sigf(float v) {
    return __fdividef(1.0f, 1.0f + __expf(-v));
}
__device__ __forceinline__ float tanhfast(float v) {
    float ax = fabsf(v);
    float e = __expf(-2.0f * ax);
    float t = __fdividef(1.0f - e, 1.0f + e);
    return copysignf(t, v);
}

// ------------------------------ K1: scores (+init) --------------------------
__global__ void k_scores(const float* __restrict__ x,
                         const float* __restrict__ W1, const float* __restrict__ b1,
                         const float* __restrict__ W2, const float* __restrict__ b2) {
    __shared__ float W1s[NDA][NI + 1];
    __shared__ float W2s[NR][NDA + 1];
    __shared__ float b1s[NDA];
    __shared__ float b2s[NR];
    __shared__ float xr[8][NI];
    __shared__ float ssm[8][NDA + 1];
    int tid = threadIdx.x;

    if (blockIdx.x == 0) {
        if (tid < 128) g_flags[tid] = 0u;
    }

    for (int idx = tid; idx < NDA * NI; idx += 256) W1s[idx / NI][idx % NI] = W1[idx];
    for (int idx = tid; idx < NR * NDA; idx += 256) W2s[idx / NDA][idx % NDA] = W2[idx];
    if (tid < NDA) b1s[tid] = b1[tid];
    if (tid < NR)  b2s[tid] = b2[tid];
    __syncthreads();

    int w = tid >> 5, lane = tid & 31;
    int bt = blockIdx.x * 8 + w;
    const float* xp = x + (size_t)bt * NI;
    for (int i = lane; i < NI; i += 32) xr[w][i] = xp[i];
    __syncwarp();
    for (int d = lane; d < NDA; d += 32) {
        float acc = b1s[d];
        #pragma unroll 16
        for (int i = 0; i < NI; i++) acc = fmaf(xr[w][i], W1s[d][i], acc);
        ssm[w][d] = tanhf(acc);
    }
    __syncwarp();
    if (lane < NR) {
        float acc = b2s[lane];
        #pragma unroll
        for (int d = 0; d < NDA; d++) acc = fmaf(ssm[w][d], W2s[lane][d], acc);
        int b = bt >> 9, t = bt & 511;
        g_S[((size_t)b * NR + lane) * NT + t] = acc;
    }
}

// --------------- K2: max over t, exp, prefix-sum denominators ---------------
__global__ void k_maxexpdinv() {
    int br = blockIdx.x;
    int b = br / NR, r = br % NR;
    int tid = threadIdx.x;
    int w = tid >> 5, lane = tid & 31;
    const float* Sp = g_S + (size_t)br * NT;
    float4 v = *(const float4*)(Sp + 4 * tid);

    __shared__ float red[4];
    __shared__ float wsum[4];
    float m = fmaxf(fmaxf(v.x, v.y), fmaxf(v.z, v.w));
    for (int o = 16; o; o >>= 1) m = fmaxf(m, __shfl_xor_sync(~0u, m, o));
    if (lane == 0) red[w] = m;
    __syncthreads();
    m = fmaxf(fmaxf(red[0], red[1]), fmaxf(red[2], red[3]));

    float e0 = __expf(v.x - m), e1 = __expf(v.y - m);
    float e2 = __expf(v.z - m), e3 = __expf(v.w - m);
    float ls = e0 + e1 + e2 + e3;

    float s = ls;
    for (int o = 1; o < 32; o <<= 1) {
        float n = __shfl_up_sync(~0u, s, o);
        if (lane >= o) s += n;
    }
    if (lane == 31) wsum[w] = s;
    __syncthreads();
    float base = 0.0f;
    #pragma unroll
    for (int ww = 0; ww < 4; ww++) if (ww < w) base += wsum[ww];

    float excl = base + s - ls;
    float d0 = excl + e0;
    float d1 = d0 + e1;
    float d2 = d1 + e2;
    float d3 = d2 + e3;

    int t0 = 4 * tid;
    size_t a0 = ((size_t)b * NT + t0) * NR + r;
    g_E[a0]            = e0;
    g_E[a0 + NR]       = e1;
    g_E[a0 + 2 * NR]   = e2;
    g_E[a0 + 3 * NR]   = e3;
    g_Dinv[a0]          = __fdividef(1.0f, d0);
    g_Dinv[a0 + NR]     = __fdividef(1.0f, d1);
    g_Dinv[a0 + 2 * NR] = __fdividef(1.0f, d2);
    g_Dinv[a0 + 3 * NR] = __fdividef(1.0f, d3);
}

// ------- K3: M via per-chunk recompute; writes MT[t][i][b] ------------------
__global__ void k_attnM(const float* __restrict__ x) {
    int bc = blockIdx.x;
    int b = bc >> 3, c = bc & 7;
    int i = threadIdx.x;
    float N[NR];
    #pragma unroll
    for (int r = 0; r < NR; r++) N[r] = 0.0f;

    const float* xb = x + ((size_t)b * NT) * NI + i;
    const float* Eb = g_E + ((size_t)b * NT) * NR;
    const float* Db = g_Dinv + ((size_t)b * NT) * NR;

    int tstart = c * 64;
    for (int t = 0; t < tstart; t++) {
        float xv = xb[(size_t)t * NI];
        #pragma unroll
        for (int r = 0; r < NR; r++)
            N[r] = fmaf(Eb[(size_t)t * NR + r], xv, N[r]);
    }
    for (int tl = 0; tl < 64; tl++) {
        int t = tstart + tl;
        float xv = xb[(size_t)t * NI];
        float acc = 0.0f;
        #pragma unroll
        for (int r = 0; r < NR; r++) {
            N[r] = fmaf(Eb[(size_t)t * NR + r], xv, N[r]);
            acc = fmaf(N[r], Db[(size_t)t * NR + r], acc);
        }
        g_MT[((size_t)t * NI + i) * 64 + b] = acc * 0.05f;
    }
}

// ---------------- K4: k-split group LSTM. 16 groups x 8 CTAs ----------------
// Group gb owns batches [4gb,4gb+4). CTA j of group:
//   holds W_hh rows k in [32j,32j+32), W_ih rows i in [16j,16j+16) (all 1024 cols)
//   produces h for hd in [32j,32j+32) (its OWN next k-slice -> h never leaves CTA)
// Exchange: gate partials only, via L2 inbox + per-CTA flags (7 peers).
// Thread: s = tid>>8 (k-half), cg = tid&255 -> cols [4cg,4cg+4).
// smem floats: Wh 32768 | Wi 16384 | gred 1024 | hdup 256 | Mdup 256 | csml 128 | bsl 128
#define LSTM_SMEM ((32768 + 16384 + 1024 + 256 + 256 + 128 + 128) * 4)

__global__ void __launch_bounds__(512, 1) k_lstm(const float* __restrict__ Whh,
                                                 const float* __restrict__ Wih,
                                                 const float* __restrict__ bias) {
    extern __shared__ float sm[];
    float* Wh   = sm;                  // [k=32][1024]
    float* Wi   = Wh + 32768;          // [i=16][1024]
    float* gred = Wi + 16384;          // [ks=2][b=4][128 own-cols]
    float* hdup = gred + 1024;         // [k=32][8] = (b0,b0,b1,b1,b2,b2,b3,b3)
    float* Mdup = hdup + 256;          // [2][i=16][8]
    float* csml = Mdup + 256;          // [b=4][32]
    float* bsl  = csml + 128;          // [128] own-col bias

    int bk = blockIdx.x;
    int tid = threadIdx.x;
    int j = bk & 7, gb = bk >> 3;
    int b0 = gb * 4;
    int base = bk & ~7;
    int s = tid >> 8, cg = tid & 255;
    int c0 = cg * 4;
    int gidx = c0 >> 8;                    // gate of my cols
    int own = (c0 & 255) >> 5;             // hd-owner CTA of my cols
    int loc = gidx * 32 + (c0 & 31);       // owner-local col index (4 contiguous)

    // weight slices (fp32)
    for (int idx = tid; idx < 8192; idx += 512) {
        int k = idx >> 8, cc = (idx & 255) * 4;
        *(float4*)&Wh[k * 1024 + cc] =
            *(const float4*)&Whh[(size_t)(32 * j + k) * G4 + cc];
    }
    for (int idx = tid; idx < 4096; idx += 512) {
        int i = idx >> 8, cc = (idx & 255) * 4;
        *(float4*)&Wi[i * 1024 + cc] =
            *(const float4*)&Wih[(size_t)(16 * j + i) * G4 + cc];
    }
    if (tid < 128) {
        bsl[tid] = bias[(tid >> 5) * NH + 32 * j + (tid & 31)];
        csml[tid] = 1.0f;
    }
    if (tid < 256) hdup[tid] = 1.0f;       // h_0 = 1 (duplicated trivially)
    if (tid < 16) {                        // M_0 -> Mdup[0]
        float4 m = __ldcg((const float4*)&g_MT[(size_t)(16 * j + tid) * 64 + b0]);
        *(float4*)&Mdup[tid * 8]     = make_float4(m.x, m.x, m.y, m.y);
        *(float4*)&Mdup[tid * 8 + 4] = make_float4(m.z, m.z, m.w, m.w);
    }
    __syncthreads();

    // gx partials for t=0
    unsigned long long gx[8];
    #pragma unroll
    for (int q = 0; q < 8; q++) gx[q] = 0ull;
    {
        const float* mp = Mdup + (s * 8) * 8;
        const float* wp = Wi + (s * 8) * 1024 + c0;
        #pragma unroll
        for (int k = 0; k < 8; k++) {
            ulonglong2 hA = *(const ulonglong2*)mp;
            ulonglong2 hB = *(const ulonglong2*)(mp + 4);
            ulonglong2 wv = *(const ulonglong2*)wp;
            ffma2(gx[0], wv.x, hA.x); ffma2(gx[1], wv.x, hA.y);
            ffma2(gx[2], wv.x, hB.x); ffma2(gx[3], wv.x, hB.y);
            ffma2(gx[4], wv.y, hA.x); ffma2(gx[5], wv.y, hA.y);
            ffma2(gx[6], wv.y, hB.x); ffma2(gx[7], wv.y, hB.y);
            mp += 8; wp += 1024;
        }
    }

    for (int t = 0; t < NT; t++) {
        int ph = t & 1;

        // prefetch M_{t+1}
        float4 mreg;
        if (tid < 16)
            mreg = __ldcg((const float4*)&g_MT[
                (size_t)(((t + 1) & (NT - 1)) * NI + 16 * j + tid) * 64 + b0]);

        // recurrent dot over own k-half; acc initialized with gx partials
        unsigned long long a[8];
        #pragma unroll
        for (int q = 0; q < 8; q++) a[q] = gx[q];
        {
            const float* hp = hdup + (s * 16) * 8;
            const float* wp = Wh + (s * 16) * 1024 + c0;
            #pragma unroll
            for (int k = 0; k < 16; k++) {
                ulonglong2 hA = *(const ulonglong2*)hp;
                ulonglong2 hB = *(const ulonglong2*)(hp + 4);
                ulonglong2 wv = *(const ulonglong2*)wp;
                ffma2(a[0], wv.x, hA.x); ffma2(a[1], wv.x, hA.y);
                ffma2(a[2], wv.x, hB.x); ffma2(a[3], wv.x, hB.y);
                ffma2(a[4], wv.y, hA.x); ffma2(a[5], wv.y, hA.y);
                ffma2(a[6], wv.y, hB.x); ffma2(a[7], wv.y, hB.y);
                hp += 8; wp += 1024;
            }
        }
        // write partials: own cols -> smem gred; remote -> peer's gmem inbox
        if (own == j) {
            #pragma unroll
            for (int b = 0; b < 4; b++) {
                *(unsigned long long*)&gred[(s * 4 + b) * 128 + loc]     = a[b];
                *(unsigned long long*)&gred[(s * 4 + b) * 128 + loc + 2] = a[4 + b];
            }
        } else {
            // slab for (consumer=base+own, ph, src=j, kseg=s): 512 floats
            float* ib = g_inbox
                + ((((size_t)(base + own) * 2 + ph) * 8 + j) * 2 + s) * 512;
            #pragma unroll
            for (int b = 0; b < 4; b++) {
                *(unsigned long long*)&ib[b * 128 + loc]     = a[b];
                *(unsigned long long*)&ib[b * 128 + loc + 2] = a[4 + b];
            }
        }
        // park M_{t+1} (dup)
        if (tid < 16) {
            float* md = Mdup + ((t + 1) & 1) * 128 + tid * 8;
            *(float4*)md       = make_float4(mreg.x, mreg.x, mreg.y, mreg.y);
            *(float4*)(md + 4) = make_float4(mreg.z, mreg.z, mreg.w, mreg.w);
        }
        __syncthreads();                               // (A) gred/inbox/Mdup done

        if (tid == 0)
            asm volatile("st.release.gpu.global.u32 [%0], %1;"
                         :: "l"(&g_flags[bk]), "r"((unsigned)(t + 1)) : "memory");

        // gx for t+1 (straggle window)
        #pragma unroll
        for (int q = 0; q < 8; q++) gx[q] = 0ull;
        {
            const float* mp = Mdup + ((t + 1) & 1) * 128 + (s * 8) * 8;
            const float* wp = Wi + (s * 8) * 1024 + c0;
            #pragma unroll
            for (int k = 0; k < 8; k++) {
                ulonglong2 hA = *(const ulonglong2*)mp;
                ulonglong2 hB = *(const ulonglong2*)(mp + 4);
                ulonglong2 wv = *(const ulonglong2*)wp;
                ffma2(gx[0], wv.x, hA.x); ffma2(gx[1], wv.x, hA.y);
                ffma2(gx[2], wv.x, hB.x); ffma2(gx[3], wv.x, hB.y);
                ffma2(gx[4], wv.y, hA.x); ffma2(gx[5], wv.y, hA.y);
                ffma2(gx[6], wv.y, hB.x); ffma2(gx[7], wv.y, hB.y);
                mp += 8; wp += 1024;
            }
        }

        // poll 7 peer flags
        if (tid < 7) {
            int pj = tid + (tid >= j ? 1 : 0);
            const unsigned* fp = &g_flags[base + pj];
            unsigned v;
            do {
                asm volatile("ld.acquire.gpu.global.u32 %0, [%1];"
                             : "=r"(v) : "l"(fp));
            } while (v < (unsigned)(t + 1));
        }
        __syncthreads();                               // (B) peers' partials ready

        // gates for own hd slice: 32 hd x 4 b
        if (tid < 128) {
            int hd_l = tid & 31, bb = tid >> 5;
            float gv[4];
            #pragma unroll
            for (int g2 = 0; g2 < 4; g2++) {
                int lc = g2 * 32 + hd_l;
                float ssum = gred[(0 * 4 + bb) * 128 + lc]
                           + gred[(1 * 4 + bb) * 128 + lc] + bsl[lc];
                #pragma unroll
                for (int src = 0; src < 8; src++) {
                    if (src != j) {
                        // slabs for (consumer=bk, ph, src): kseg 0 at +0, kseg 1 at +512
                        const float* ib = g_inbox
                            + ((((size_t)bk * 2 + ph) * 8 + src) * 2) * 512;
                        ssum += __ldcg(&ib[bb * 128 + lc]);
                        ssum += __ldcg(&ib[512 + bb * 128 + lc]);
                    }
                }
                gv[g2] = ssum;
            }
            float i_t = sigf(gv[0]);
            float f_t = sigf(gv[1]);
            float g_t = tanhfast(gv[2]);
            float o_t = sigf(gv[3]);
            float cc = f_t * csml[tid] + i_t * g_t;
            csml[tid] = cc;
            float hval = o_t * tanhfast(cc);
            *(float2*)&hdup[hd_l * 8 + bb * 2] = make_float2(hval, hval);
            if (t == NT - 1)
                g_hT[(32 * j + hd_l) * 64 + b0 + bb] = hval;
        }
        __syncthreads();                               // (C) hdup/csml ready
    }
}

// ------------------------------ K5: head + softmax --------------------------
__global__ void k_head(const float* __restrict__ Wfc, const float* __restrict__ bfc,
                       float* __restrict__ out) {
    int b = blockIdx.x;
    int lane = threadIdx.x;
    __shared__ float hsm[NH];
    for (int k = lane; k < NH; k += 32) hsm[k] = g_hT[k * 64 + b];
    __syncwarp();
    float l = -1e30f;
    if (lane < NC) {
        float acc = bfc[lane];
        #pragma unroll 8
        for (int k = 0; k < NH; k++) acc = fmaf(hsm[k], Wfc[lane * NH + k], acc);
        l = acc;
    }
    float m = l;
    for (int o = 16; o; o >>= 1) m = fmaxf(m, __shfl_xor_sync(~0u, m, o));
    float e = (lane < NC) ? __expf(l - m) : 0.0f;
    float s = e;
    for (int o = 16; o; o >>= 1) s += __shfl_xor_sync(~0u, s, o);
    if (lane < NC) out[b * NC + lane] = e / s;
}

// ------------------------------ launch --------------------------------------
extern "C" void kernel_launch(void* const* d_in, const int* in_sizes, int n_in,
                              void* d_out, int out_size) {
    const float* x    = (const float*)d_in[0];
    const float* W_ih = (const float*)d_in[1];
    const float* W_hh = (const float*)d_in[2];
    const float* b    = (const float*)d_in[3];
    const float* W1   = (const float*)d_in[4];
    const float* b1   = (const float*)d_in[5];
    const float* W2   = (const float*)d_in[6];
    const float* b2   = (const float*)d_in[7];
    const float* Wfc  = (const float*)d_in[8];
    const float* bfc  = (const float*)d_in[9];
    float* out = (float*)d_out;

    cudaFuncSetAttribute(k_lstm, cudaFuncAttributeMaxDynamicSharedMemorySize, LSTM_SMEM);

    k_scores<<<4096, 256>>>(x, W1, b1, W2, b2);            // idx 0
    k_maxexpdinv<<<NB * NR, 128>>>();                      // idx 1
    k_attnM<<<NB * 8, 128>>>(x);                           // idx 2
    k_lstm<<<128, 512, LSTM_SMEM>>>(W_hh, W_ih, b);        // idx 3 (ncu slot)
    k_head<<<NB, 32>>>(Wfc, bfc, out);                     // idx 4
}

// round 16
// speedup vs baseline: 1.0396x; 1.0396x over previous
#include <cuda_runtime.h>
#include <cuda_bf16.h>
#include <cstdint>

#define NB 64
#define NT 512
#define NI 128
#define NH 256
#define NR 20
#define NDA 50
#define NC 10
#define G4 1024

// ----------------------------- device scratch ------------------------------
__device__ float g_S   [NB * NR * NT];              // [b][r][t]
__device__ float g_E   [NB * NT * NR];              // [b][t][r]
__device__ float g_Dinv[NB * NT * NR];              // [b][t][r]
__device__ float g_MT  [(size_t)NT * NI * NB];      // [t][i][b]
__device__ float g_h   [2][NH * 64];                // [buf][hd*64 + b]
__device__ unsigned g_flags[128];                   // per-CTA step flags

__device__ __forceinline__ void ffma2(unsigned long long& acc,
                                      unsigned long long a,
                                      unsigned long long b) {
    asm("fma.rn.f32x2 %0, %1, %2, %0;" : "+l"(acc) : "l"(a), "l"(b));
}
__device__ __forceinline__ float sigf(float v) {
    return __fdividef(1.0f, 1.0f + __expf(-v));
}
__device__ __forceinline__ float tanhfast(float v) {
    float ax = fabsf(v);
    float e = __expf(-2.0f * ax);
    float t = __fdividef(1.0f - e, 1.0f + e);
    return copysignf(t, v);
}

// ------------------------------ K1: scores (+init) --------------------------
__global__ void k_scores(const float* __restrict__ x,
                         const float* __restrict__ W1, const float* __restrict__ b1,
                         const float* __restrict__ W2, const float* __restrict__ b2) {
    __shared__ float W1s[NDA][NI + 1];
    __shared__ float W2s[NR][NDA + 1];
    __shared__ float b1s[NDA];
    __shared__ float b2s[NR];
    __shared__ float xr[8][NI];
    __shared__ float ssm[8][NDA + 1];
    int tid = threadIdx.x;

    if (blockIdx.x == 0) {
        for (int j = tid; j < NH * 64; j += 256) g_h[0][j] = 1.0f;
        if (tid < 128) g_flags[tid] = 0u;
    }

    for (int idx = tid; idx < NDA * NI; idx += 256) W1s[idx / NI][idx % NI] = W1[idx];
    for (int idx = tid; idx < NR * NDA; idx += 256) W2s[idx / NDA][idx % NDA] = W2[idx];
    if (tid < NDA) b1s[tid] = b1[tid];
    if (tid < NR)  b2s[tid] = b2[tid];
    __syncthreads();

    int w = tid >> 5, lane = tid & 31;
    int bt = blockIdx.x * 8 + w;
    const float* xp = x + (size_t)bt * NI;
    for (int i = lane; i < NI; i += 32) xr[w][i] = xp[i];
    __syncwarp();
    for (int d = lane; d < NDA; d += 32) {
        float acc = b1s[d];
        #pragma unroll 16
        for (int i = 0; i < NI; i++) acc = fmaf(xr[w][i], W1s[d][i], acc);
        ssm[w][d] = tanhf(acc);
    }
    __syncwarp();
    if (lane < NR) {
        float acc = b2s[lane];
        #pragma unroll
        for (int d = 0; d < NDA; d++) acc = fmaf(ssm[w][d], W2s[lane][d], acc);
        int b = bt >> 9, t = bt & 511;
        g_S[((size_t)b * NR + lane) * NT + t] = acc;
    }
}

// --------------- K2: max over t, exp, prefix-sum denominators ---------------
__global__ void k_maxexpdinv() {
    int br = blockIdx.x;
    int b = br / NR, r = br % NR;
    int tid = threadIdx.x;
    int w = tid >> 5, lane = tid & 31;
    const float* Sp = g_S + (size_t)br * NT;
    float4 v = *(const float4*)(Sp + 4 * tid);

    __shared__ float red[4];
    __shared__ float wsum[4];
    float m = fmaxf(fmaxf(v.x, v.y), fmaxf(v.z, v.w));
    for (int o = 16; o; o >>= 1) m = fmaxf(m, __shfl_xor_sync(~0u, m, o));
    if (lane == 0) red[w] = m;
    __syncthreads();
    m = fmaxf(fmaxf(red[0], red[1]), fmaxf(red[2], red[3]));

    float e0 = __expf(v.x - m), e1 = __expf(v.y - m);
    float e2 = __expf(v.z - m), e3 = __expf(v.w - m);
    float ls = e0 + e1 + e2 + e3;

    float s = ls;
    for (int o = 1; o < 32; o <<= 1) {
        float n = __shfl_up_sync(~0u, s, o);
        if (lane >= o) s += n;
    }
    if (lane == 31) wsum[w] = s;
    __syncthreads();
    float base = 0.0f;
    #pragma unroll
    for (int ww = 0; ww < 4; ww++) if (ww < w) base += wsum[ww];

    float excl = base + s - ls;
    float d0 = excl + e0;
    float d1 = d0 + e1;
    float d2 = d1 + e2;
    float d3 = d2 + e3;

    int t0 = 4 * tid;
    size_t a0 = ((size_t)b * NT + t0) * NR + r;
    g_E[a0]            = e0;
    g_E[a0 + NR]       = e1;
    g_E[a0 + 2 * NR]   = e2;
    g_E[a0 + 3 * NR]   = e3;
    g_Dinv[a0]          = __fdividef(1.0f, d0);
    g_Dinv[a0 + NR]     = __fdividef(1.0f, d1);
    g_Dinv[a0 + 2 * NR] = __fdividef(1.0f, d2);
    g_Dinv[a0 + 3 * NR] = __fdividef(1.0f, d3);
}

// ------- K3: M via per-chunk recompute; writes MT[t][i][b] ------------------
__global__ void k_attnM(const float* __restrict__ x) {
    int bc = blockIdx.x;
    int b = bc >> 3, c = bc & 7;
    int i = threadIdx.x;
    float N[NR];
    #pragma unroll
    for (int r = 0; r < NR; r++) N[r] = 0.0f;

    const float* xb = x + ((size_t)b * NT) * NI + i;
    const float* Eb = g_E + ((size_t)b * NT) * NR;
    const float* Db = g_Dinv + ((size_t)b * NT) * NR;

    int tstart = c * 64;
    for (int t = 0; t < tstart; t++) {
        float xv = xb[(size_t)t * NI];
        #pragma unroll
        for (int r = 0; r < NR; r++)
            N[r] = fmaf(Eb[(size_t)t * NR + r], xv, N[r]);
    }
    for (int tl = 0; tl < 64; tl++) {
        int t = tstart + tl;
        float xv = xb[(size_t)t * NI];
        float acc = 0.0f;
        #pragma unroll
        for (int r = 0; r < NR; r++) {
            N[r] = fmaf(Eb[(size_t)t * NR + r], xv, N[r]);
            acc = fmaf(N[r], Db[(size_t)t * NR + r], acc);
        }
        g_MT[((size_t)t * NI + i) * 64 + b] = acc * 0.05f;
    }
}

// -------- K4: batch-split LSTM. 2 groups x 64 CTAs, 512 threads each --------
// Group grp = bk>>6 owns batches [32grp, 32grp+32); CTA jj = bk&63 owns
// h-dims [4jj,4jj+4) -> 16 gate cols (c = gate*4 + hdl) for its 32 batches.
// Thread (p=tid&7: 4 b, qh=(tid>>3)&3: 4 cols, seg=tid>>5: k-16th of 16).
// smem floats: hs 256*36 | Ws2 256*32 | Wis2 128*32 | Mss 128*36 | gred 16*16*32
//              | csml 128 | bsl 16
#define HSS 36
#define LSTM_SMEM ((256 * HSS + 256 * 32 + 128 * 32 + 128 * HSS + 16 * 16 * 32 + 128 + 16) * 4)

__global__ void __launch_bounds__(512, 1) k_lstm(const float* __restrict__ Whh,
                                                 const float* __restrict__ Wih,
                                                 const float* __restrict__ bias) {
    extern __shared__ float sm[];
    float* hs   = sm;                        // [k=256][HSS]
    float* Ws2  = hs + 256 * HSS;            // Whh slice pair-dup [k=256][32]
    float* Wis2 = Ws2 + 256 * 32;            // Wih slice pair-dup [i=128][32]
    float* Mss  = Wis2 + 128 * 32;           // parked M tile [i=128][HSS]
    float* gred = Mss + 128 * HSS;           // [seg=16][c=16][b=32]
    float* csml = gred + 16 * 16 * 32;       // c state (128: hdl*32+b)
    float* bsl  = csml + 128;                // bias slice (16)

    int bk = blockIdx.x;
    int tid = threadIdx.x;
    int grp = bk >> 6, jj = bk & 63;
    int bbase = 32 * grp;
    int p = tid & 7, qh = (tid >> 3) & 3, seg = tid >> 5;

    // W slices: col c: gate = c>>2, hdl = c&3 -> global col gate*256 + 4jj + hdl
    for (int idx = tid; idx < NH * 16; idx += 512) {
        int k = idx >> 4, c = idx & 15;
        float w = Whh[(size_t)k * G4 + (c >> 2) * NH + 4 * jj + (c & 3)];
        Ws2[k * 32 + c * 2]     = w;
        Ws2[k * 32 + c * 2 + 1] = w;
    }
    for (int idx = tid; idx < NI * 16; idx += 512) {
        int k = idx >> 4, c = idx & 15;
        float w = Wih[(size_t)k * G4 + (c >> 2) * NH + 4 * jj + (c & 3)];
        Wis2[k * 32 + c * 2]     = w;
        Wis2[k * 32 + c * 2 + 1] = w;
    }
    if (tid < 16) bsl[tid] = bias[(tid >> 2) * NH + 4 * jj + (tid & 3)];
    if (tid < 128) csml[tid] = 1.0f;

    // ---- prologue: stage M_0, compute gx partials for t=0 ----
    {
        #pragma unroll
        for (int jv = 0; jv < 2; jv++) {
            int idx = tid + jv * 512;            // f4 index over [128 i][8 f4]
            int row = idx >> 3, c4 = (idx & 7) * 4;
            float4 m = __ldcg((const float4*)&g_MT[(size_t)row * 64 + bbase + c4]);
            *(float4*)&Mss[row * HSS + c4] = m;
        }
    }
    __syncthreads();

    unsigned long long gx[8];
    #pragma unroll
    for (int q = 0; q < 8; q++) gx[q] = 0ull;
    {   // i-segment [seg*8, seg*8+8)
        const float* mp = Mss + (seg * 8) * HSS + 4 * p;
        const float* wp = Wis2 + (seg * 8) * 32 + 8 * qh;
        #pragma unroll
        for (int k = 0; k < 8; k++) {
            ulonglong2 hv = *(const ulonglong2*)mp;
            ulonglong2 w0 = *(const ulonglong2*)wp;
            ulonglong2 w1 = *(const ulonglong2*)(wp + 4);
            ffma2(gx[0], hv.x, w0.x); ffma2(gx[1], hv.y, w0.x);
            ffma2(gx[2], hv.x, w0.y); ffma2(gx[3], hv.y, w0.y);
            ffma2(gx[4], hv.x, w1.x); ffma2(gx[5], hv.y, w1.x);
            ffma2(gx[6], hv.x, w1.y); ffma2(gx[7], hv.y, w1.y);
            mp += HSS; wp += 32;
        }
    }

    int bbg = tid & 31, hdl = (tid >> 5) & 3;    // gate mapping (tid<128)

    for (int t = 0; t < NT; t++) {
        const float* hin = g_h[t & 1];
        float* hout = g_h[(t + 1) & 1];
        const float* mnext = g_MT + (size_t)((t + 1) & (NT - 1)) * (NI * 64);

        // issue h loads (16 floats/thread) then M_{t+1} (8 floats/thread)
        float4 rh[4], rm[2];
        #pragma unroll
        for (int jv = 0; jv < 4; jv++) {
            int idx = tid + jv * 512;            // f4 over [256 k][8 f4]
            int row = idx >> 3, c4 = (idx & 7) * 4;
            rh[jv] = __ldcg((const float4*)&hin[row * 64 + bbase + c4]);
        }
        #pragma unroll
        for (int jv = 0; jv < 2; jv++) {
            int idx = tid + jv * 512;
            int row = idx >> 3, c4 = (idx & 7) * 4;
            rm[jv] = __ldcg((const float4*)&mnext[(size_t)row * 64 + bbase + c4]);
        }

        // stage h
        #pragma unroll
        for (int jv = 0; jv < 4; jv++) {
            int idx = tid + jv * 512;
            int row = idx >> 3, c4 = (idx & 7) * 4;
            *(float4*)&hs[row * HSS + c4] = rh[jv];
        }
        __syncthreads();                             // (1) hs ready

        unsigned long long a[8];
        #pragma unroll
        for (int q = 0; q < 8; q++) a[q] = gx[q];
        {   // recurrent dot: seg's k-16th [seg*16, seg*16+16)
            const float* hp = hs + (seg * 16) * HSS + 4 * p;
            const float* wp = Ws2 + (seg * 16) * 32 + 8 * qh;
            #pragma unroll 8
            for (int k = 0; k < 16; k++) {
                ulonglong2 hv = *(const ulonglong2*)hp;
                ulonglong2 w0 = *(const ulonglong2*)wp;
                ulonglong2 w1 = *(const ulonglong2*)(wp + 4);
                ffma2(a[0], hv.x, w0.x); ffma2(a[1], hv.y, w0.x);
                ffma2(a[2], hv.x, w0.y); ffma2(a[3], hv.y, w0.y);
                ffma2(a[4], hv.x, w1.x); ffma2(a[5], hv.y, w1.x);
                ffma2(a[6], hv.x, w1.y); ffma2(a[7], hv.y, w1.y);
                hp += HSS; wp += 32;
            }
        }
        {   // gred[seg][col][b]: cols 4qh..4qh+3, b 4p..4p+3
            float* gr = gred + (seg * 16 + 4 * qh) * 32 + 4 * p;
            ulonglong2 v;
            v.x = a[0]; v.y = a[1]; *(ulonglong2*)gr        = v;
            v.x = a[2]; v.y = a[3]; *(ulonglong2*)(gr + 32) = v;
            v.x = a[4]; v.y = a[5]; *(ulonglong2*)(gr + 64) = v;
            v.x = a[6]; v.y = a[7]; *(ulonglong2*)(gr + 96) = v;
        }
        // park M_{t+1}
        #pragma unroll
        for (int jv = 0; jv < 2; jv++) {
            int idx = tid + jv * 512;
            int row = idx >> 3, c4 = (idx & 7) * 4;
            *(float4*)&Mss[row * HSS + c4] = rm[jv];
        }
        __syncthreads();                             // (2) gred + Mss ready

        if (tid < 128) {
            float gv[4];
            #pragma unroll
            for (int g2 = 0; g2 < 4; g2++) {
                int c = g2 * 4 + hdl;
                float s = 0.0f;
                #pragma unroll
                for (int o = 0; o < 16; o++) s += gred[(o * 16 + c) * 32 + bbg];
                gv[g2] = s + bsl[c];
            }
            float i_t = sigf(gv[0]);
            float f_t = sigf(gv[1]);
            float g_t = tanhfast(gv[2]);
            float o_t = sigf(gv[3]);
            float cc = f_t * csml[tid] + i_t * g_t;
            csml[tid] = cc;
            __stcg(&hout[(4 * jj + hdl) * 64 + bbase + bbg], o_t * tanhfast(cc));
        }
        __syncthreads();                             // (3) h stores issued

        if (tid == 0)
            asm volatile("st.release.gpu.global.u32 [%0], %1;"
                         :: "l"(&g_flags[bk]), "r"((unsigned)(t + 1)) : "memory");

        // gx for t+1 in the straggle window
        #pragma unroll
        for (int q = 0; q < 8; q++) gx[q] = 0ull;
        {
            const float* mp = Mss + (seg * 8) * HSS + 4 * p;
            const float* wp = Wis2 + (seg * 8) * 32 + 8 * qh;
            #pragma unroll
            for (int k = 0; k < 8; k++) {
                ulonglong2 hv = *(const ulonglong2*)mp;
                ulonglong2 w0 = *(const ulonglong2*)wp;
                ulonglong2 w1 = *(const ulonglong2*)(wp + 4);
                ffma2(gx[0], hv.x, w0.x); ffma2(gx[1], hv.y, w0.x);
                ffma2(gx[2], hv.x, w0.y); ffma2(gx[3], hv.y, w0.y);
                ffma2(gx[4], hv.x, w1.x); ffma2(gx[5], hv.y, w1.x);
                ffma2(gx[6], hv.x, w1.y); ffma2(gx[7], hv.y, w1.y);
                mp += HSS; wp += 32;
            }
        }

        // wait: 64 pollers, only this group's flags
        if (tid < 64) {
            unsigned v;
            const unsigned* fp = &g_flags[64 * grp + tid];
            do {
                asm volatile("ld.acquire.gpu.global.u32 %0, [%1];"
                             : "=r"(v) : "l"(fp));
            } while (v < (unsigned)(t + 1));
        }
        __syncthreads();                             // (4) barrier release
    }
}

// ------------------------------ K5: head + softmax --------------------------
__global__ void k_head(const float* __restrict__ Wfc, const float* __restrict__ bfc,
                       float* __restrict__ out) {
    int b = blockIdx.x;
    int lane = threadIdx.x;
    __shared__ float hsm[NH];
    for (int k = lane; k < NH; k += 32) hsm[k] = g_h[0][k * 64 + b];
    __syncwarp();
    float l = -1e30f;
    if (lane < NC) {
        float acc = bfc[lane];
        #pragma unroll 8
        for (int k = 0; k < NH; k++) acc = fmaf(hsm[k], Wfc[lane * NH + k], acc);
        l = acc;
    }
    float m = l;
    for (int o = 16; o; o >>= 1) m = fmaxf(m, __shfl_xor_sync(~0u, m, o));
    float e = (lane < NC) ? __expf(l - m) : 0.0f;
    float s = e;
    for (int o = 16; o; o >>= 1) s += __shfl_xor_sync(~0u, s, o);
    if (lane < NC) out[b * NC + lane] = e / s;
}

// ------------------------------ launch --------------------------------------
extern "C" void kernel_launch(void* const* d_in, const int* in_sizes, int n_in,
                              void* d_out, int out_size) {
    const float* x    = (const float*)d_in[0];
    const float* W_ih = (const float*)d_in[1];
    const float* W_hh = (const float*)d_in[2];
    const float* b    = (const float*)d_in[3];
    const float* W1   = (const float*)d_in[4];
    const float* b1   = (const float*)d_in[5];
    const float* W2   = (const float*)d_in[6];
    const float* b2   = (const float*)d_in[7];
    const float* Wfc  = (const float*)d_in[8];
    const float* bfc  = (const float*)d_in[9];
    float* out = (float*)d_out;

    cudaFuncSetAttribute(k_lstm, cudaFuncAttributeMaxDynamicSharedMemorySize, LSTM_SMEM);

    k_scores<<<4096, 256>>>(x, W1, b1, W2, b2);            // idx 0
    k_maxexpdinv<<<NB * NR, 128>>>();                      // idx 1
    k_attnM<<<NB * 8, 128>>>(x);                           // idx 2
    k_lstm<<<128, 512, LSTM_SMEM>>>(W_hh, W_ih, b);        // idx 3 (ncu slot)
    k_head<<<NB, 32>>>(Wfc, bfc, out);                     // idx 4
}